// round 8
// baseline (speedup 1.0000x reference)
#include <cuda_runtime.h>
#include <cstdint>

#define K_DIM 8192
#define M_DIM 8192

// gemv tiling (R3-proven)
#define ROWTILE 64
#define KC 4
#define CHUNK (K_DIM / KC)          // 2048
#define SLICE_K 64
#define NSLICES (CHUNK / SLICE_K)   // 32
#define BUF_FLOATS 4608             // W 64*64 + X 64*8
#define NBUF 3
#define SMEM_BYTES (NBUF * BUF_FLOATS * 4)   // 55296

#define SCAP 96                     // per-block smem band slots
#define BAND_CAP (1024 * 1024)

typedef unsigned long long ull;

// ---------------- static device scratch ----------------
__device__ float4 g_xt4[K_DIM * 2];            // x_hat transposed [K][8] (256 KB)
__device__ float g_ssum[256];                  // sample partials
__device__ float g_bsum[512];                  // exact |W| partials (per gemv block)
__device__ float g_tlo, g_thi;                 // conservative band bounds
__device__ float g_thresh, g_wdeq;             // exact threshold, dequant
__device__ unsigned g_bandcnt;
__device__ uint2 g_band[BAND_CAP];             // (row*8192+k, bits(w))
__device__ float g_corr[M_DIM * 8];            // correction accumulators
__device__ ull g_part[(size_t)M_DIM * KC * 4]; // f32x2 partials (1 MB)
__device__ unsigned g_done0 = 0, g_done1 = 0;  // last-block counters

// ---------------- helpers ----------------
__device__ __forceinline__ void fma2(ull& acc, ull x, ull q) {
    asm("fma.rn.f32x2 %0, %1, %2, %0;" : "+l"(acc) : "l"(x), "l"(q));
}
__device__ __forceinline__ void add2(ull& acc, ull x) {
    asm("add.rn.f32x2 %0, %1, %0;" : "+l"(acc) : "l"(x));
}
__device__ __forceinline__ void cpasync16(void* smem_dst, const void* gsrc) {
    unsigned int sa = (unsigned int)__cvta_generic_to_shared(smem_dst);
    asm volatile("cp.async.cg.shared.global [%0], [%1], 16;" :: "r"(sa), "l"(gsrc));
}
__device__ __forceinline__ void cp_commit() { asm volatile("cp.async.commit_group;"); }
__device__ __forceinline__ void cp_wait1()  { asm volatile("cp.async.wait_group 1;"); }

// ---------------- kernel A: quant_x (blocks 0-127) + sample (blocks 128-383) ----------------
__global__ void prep_kernel(const float* __restrict__ x, const float4* __restrict__ W4) {
    __shared__ float sm[8];
    __shared__ bool amLast;
    int tid = threadIdx.x;
    int lane = tid & 31, w = tid >> 5;

    if (blockIdx.x < 128) {
        // --- activation quant + zero corr ---
        int gid = blockIdx.x * 256 + tid;
        g_corr[gid] = 0.f;
        g_corr[gid + 32768] = 0.f;
        int gw = gid >> 5;
        int n = gw >> 7;
        int g = gw & 127;
        int k0 = g * 64 + lane;
        float a = x[n * K_DIM + k0];
        float b = x[n * K_DIM + k0 + 32];
        float mx = fmaxf(fabsf(a), fabsf(b));
#pragma unroll
        for (int off = 16; off; off >>= 1)
            mx = fmaxf(mx, __shfl_xor_sync(0xffffffffu, mx, off));
        float s = fmaxf(__fdiv_rn(mx, 127.0f), 1e-8f);
        float ah = rintf(__fdiv_rn(a, s)) * s;
        float bh = rintf(__fdiv_rn(b, s)) * s;
        float* xt = (float*)g_xt4;
        xt[k0 * 8 + n] = ah;
        xt[(k0 + 32) * 8 + n] = bh;
    } else {
        // --- sampled |W| estimate (first 16 MB) ---
        int sb = blockIdx.x - 128;
        int t0 = sb * 256 + tid;
        const int stride = 256 * 256;
        float s = 0.f;
#pragma unroll 4
        for (int it = 0; it < 16; it++) {
            float4 v = __ldg(W4 + t0 + (size_t)it * stride);
            s += fabsf(v.x) + fabsf(v.y) + fabsf(v.z) + fabsf(v.w);
        }
#pragma unroll
        for (int off = 16; off; off >>= 1) s += __shfl_xor_sync(0xffffffffu, s, off);
        if (lane == 0) sm[w] = s;
        __syncthreads();
        if (tid == 0) {
            float tot = 0.f;
#pragma unroll
            for (int i = 0; i < 8; i++) tot += sm[i];
            g_ssum[sb] = tot;
        }
    }

    // --- last block finalizes t-hat bounds ---
    __syncthreads();
    if (tid == 0) {
        __threadfence();
        amLast = (atomicAdd(&g_done0, 1u) == 383u);
    }
    __syncthreads();
    if (amLast) {
        __threadfence();
        float s = g_ssum[tid];
#pragma unroll
        for (int off = 16; off; off >>= 1) s += __shfl_xor_sync(0xffffffffu, s, off);
        __syncthreads();          // sm[] reuse safe
        if (lane == 0) sm[w] = s;
        __syncthreads();
        if (tid == 0) {
            float tot = 0.f;
#pragma unroll
            for (int i = 0; i < 8; i++) tot += sm[i];
            float mean_s = tot * (1.0f / 4194304.0f);
            float t_hat = 0.5f * fmaxf(mean_s, 1e-5f);
            g_tlo = t_hat * 0.998f;
            g_thi = t_hat * 1.002f;
            g_bandcnt = 0u;
            g_done0 = 0u;
        }
    }
}

// ---------------- kernel B: SINGLE fused pass over W (trimmed inner loop) ----------------
__global__ void __launch_bounds__(256, 4) gemv_fused_kernel(const float* __restrict__ W) {
    extern __shared__ float smem[];
    __shared__ uint2 s_band[SCAP];
    __shared__ int s_cnt;
    __shared__ unsigned s_gbase;
    __shared__ bool amLast;
    __shared__ float smf[8];

    const float tlo = g_tlo, thi = g_thi;
    const int tid = threadIdx.x;
    const int lane = tid & 31, warp = tid >> 5;
    const int rt = blockIdx.x >> 2;            // 0..127 row tiles
    const int kc = blockIdx.x & 3;             // 0..3 k chunks
    const int rowbase = rt * ROWTILE;
    const int k0 = kc * CHUNK;
    const float* xt = (const float*)g_xt4;
    if (tid == 0) s_cnt = 0;

    auto stage = [&](int s) {
        float* buf = smem + (s % NBUF) * BUF_FLOATS;
        float* bufX = buf + ROWTILE * SLICE_K;
        int base_k = k0 + s * SLICE_K;
#pragma unroll
        for (int i = 0; i < 4; i++) {
            int idx = tid + i * 256;
            int r = idx >> 4, c = idx & 15;
            cpasync16(buf + r * SLICE_K + ((c ^ (r & 7)) << 2),
                      W + (size_t)(rowbase + r) * K_DIM + base_k + c * 4);
        }
        if (tid < 128) cpasync16(bufX + tid * 4, xt + (size_t)base_k * 8 + tid * 4);
    };

    auto push = [&](int row, int k, float v) {
        int slot = atomicAdd(&s_cnt, 1);
        uint2 ent = make_uint2((unsigned)(row * K_DIM + k), __float_as_uint(v));
        if (slot < SCAP) s_band[slot] = ent;
        else {
            unsigned gp = atomicAdd(&g_bandcnt, 1u);
            if (gp < BAND_CAP) g_band[gp] = ent;
        }
    };

    ull a0 = 0, a1 = 0, a2 = 0, a3 = 0;
    ull b0 = 0, b1 = 0, b2 = 0, b3 = 0;
    float sabs = 0.f;

    stage(0); cp_commit();
    stage(1); cp_commit();

    const int sw = lane & 7;
    for (int s = 0; s < NSLICES; s++) {
        cp_wait1();
        __syncthreads();
        if (s + 2 < NSLICES) stage(s + 2);
        cp_commit();

        const float* buf = smem + (s % NBUF) * BUF_FLOATS;
        const ulonglong2* Xb = (const ulonglong2*)(buf + ROWTILE * SLICE_K);
#pragma unroll
        for (int step = 0; step < 2; step++) {
            int kk = warp * 8 + step * 4;
            int ch = kk >> 2;
            float4 wa = *(const float4*)(buf + lane * SLICE_K + ((ch ^ sw) << 2));
            float4 wb = *(const float4*)(buf + (lane + 32) * SLICE_K + ((ch ^ sw) << 2));
            float wae[4] = {wa.x, wa.y, wa.z, wa.w};
            float wbe[4] = {wb.x, wb.y, wb.z, wb.w};
            bool band = false;
#pragma unroll
            for (int e = 0; e < 4; e++) {
                float va = wae[e], vb = wbe[e];
                float ava = fabsf(va), avb = fabsf(vb);
                sabs += ava + avb;                          // SAME expr/order as R7
                bool pa = ava > thi;
                bool pb = avb > thi;
                unsigned qau = (pa ? 0x3f800000u : 0u) | (__float_as_uint(va) & 0x80000000u);
                unsigned qbu = (pb ? 0x3f800000u : 0u) | (__float_as_uint(vb) & 0x80000000u);
                ull qa2, qb2;
                asm("mov.b64 %0, {%1, %1};" : "=l"(qa2) : "r"(qau));
                asm("mov.b64 %0, {%1, %1};" : "=l"(qb2) : "r"(qbu));
                ulonglong2 x0 = Xb[(kk + e) * 2];
                ulonglong2 x1 = Xb[(kk + e) * 2 + 1];
                fma2(a0, x0.x, qa2); fma2(a1, x0.y, qa2);
                fma2(a2, x1.x, qa2); fma2(a3, x1.y, qa2);
                fma2(b0, x0.x, qb2); fma2(b1, x0.y, qb2);
                fma2(b2, x1.x, qb2); fma2(b3, x1.y, qb2);
                band = band | ((ava > tlo) & (!pa));        // branch-free predicate acc
                band = band | ((avb > tlo) & (!pb));
            }
            if (band) {                                     // rare: ~1 in 13 steps
                int kg = k0 + s * SLICE_K + kk;
#pragma unroll
                for (int e = 0; e < 4; e++) {
                    float va = wae[e], vb = wbe[e];
                    float ava = fabsf(va), avb = fabsf(vb);
                    if ((ava > tlo) && (ava <= thi)) push(rowbase + lane, kg + e, va);
                    if ((avb > tlo) && (avb <= thi)) push(rowbase + lane + 32, kg + e, vb);
                }
            }
        }
    }

    // ---- block reductions: abs-sum + 8->1 partials ----
    __syncthreads();
#pragma unroll
    for (int off = 16; off; off >>= 1) sabs += __shfl_xor_sync(0xffffffffu, sabs, off);
    float* absm = smem + NBUF * BUF_FLOATS - 16;
    if (lane == 0) absm[warp] = sabs;

    ulonglong2* s2 = (ulonglong2*)smem;
    s2[(warp * 64 + lane) * 2]          = make_ulonglong2(a0, a1);
    s2[(warp * 64 + lane) * 2 + 1]      = make_ulonglong2(a2, a3);
    s2[(warp * 64 + lane + 32) * 2]     = make_ulonglong2(b0, b1);
    s2[(warp * 64 + lane + 32) * 2 + 1] = make_ulonglong2(b2, b3);
    __syncthreads();

    if (tid == 0) {
        float tot = 0.f;
#pragma unroll
        for (int i = 0; i < 8; i++) tot += absm[i];
        g_bsum[blockIdx.x] = tot;
        int cnt = s_cnt; if (cnt > SCAP) cnt = SCAP;
        s_gbase = atomicAdd(&g_bandcnt, (unsigned)cnt);
    }
    if (tid < 64) {
        ull r0 = 0, r1 = 0, r2 = 0, r3 = 0;
#pragma unroll
        for (int w = 0; w < 8; w++) {
            ulonglong2 u0 = s2[(w * 64 + tid) * 2];
            ulonglong2 u1 = s2[(w * 64 + tid) * 2 + 1];
            add2(r0, u0.x); add2(r1, u0.y);
            add2(r2, u1.x); add2(r3, u1.y);
        }
        ulonglong2* P = (ulonglong2*)g_part;
        size_t p = ((size_t)(rowbase + tid) * KC + kc) * 2;
        P[p]     = make_ulonglong2(r0, r1);
        P[p + 1] = make_ulonglong2(r2, r3);
    }
    __syncthreads();
    {   // flush smem band list
        int cnt = s_cnt; if (cnt > SCAP) cnt = SCAP;
        for (int i = tid; i < cnt; i += 256) {
            unsigned gp = s_gbase + (unsigned)i;
            if (gp < BAND_CAP) g_band[gp] = s_band[i];
        }
    }

    // ---- last block: exact mean -> exact threshold (same arithmetic as R7) ----
    __syncthreads();
    if (tid == 0) {
        __threadfence();
        amLast = (atomicAdd(&g_done1, 1u) == 511u);
    }
    __syncthreads();
    if (amLast) {
        __threadfence();
        float s = g_bsum[tid] + g_bsum[tid + 256];
#pragma unroll
        for (int off = 16; off; off >>= 1) s += __shfl_xor_sync(0xffffffffu, s, off);
        if (lane == 0) smf[warp] = s;
        __syncthreads();
        if (tid == 0) {
            float tot = 0.f;
#pragma unroll
            for (int i = 0; i < 8; i++) tot += smf[i];
            float mean = tot * (1.0f / 67108864.0f);
            float m = fmaxf(mean, 1e-5f);
            float s_w = __fdiv_rn(1.0f, m);
            float wdeq = __fdiv_rn(1.0f, s_w);
            g_wdeq = wdeq;
            g_thresh = 0.5f * wdeq;
            g_done1 = 0u;
        }
    }
}

// ---------------- kernel C: replay band entries against exact threshold ----------------
__global__ void correction_kernel() {
    unsigned cnt = g_bandcnt;
    if (cnt > BAND_CAP) cnt = BAND_CAP;
    float th = g_thresh;
    for (unsigned i = blockIdx.x * 256 + threadIdx.x; i < cnt; i += 256 * 256) {
        uint2 e = g_band[i];
        float w = __uint_as_float(e.y);
        if (fabsf(w) > th) {
            float sgn = copysignf(1.0f, w);
            unsigned idx = e.x;
            int m = idx >> 13, k = idx & 8191;
            float4 x0 = g_xt4[k * 2], x1 = g_xt4[k * 2 + 1];
            float* c = g_corr + m * 8;
            atomicAdd(c + 0, sgn * x0.x);
            atomicAdd(c + 1, sgn * x0.y);
            atomicAdd(c + 2, sgn * x0.z);
            atomicAdd(c + 3, sgn * x0.w);
            atomicAdd(c + 4, sgn * x1.x);
            atomicAdd(c + 5, sgn * x1.y);
            atomicAdd(c + 6, sgn * x1.z);
            atomicAdd(c + 7, sgn * x1.w);
        }
    }
}

// ---------------- kernel D: reduce partials + corrections, apply w_deq ----------------
__global__ void finalize_out_kernel(float* __restrict__ out) {
    int m = blockIdx.x * blockDim.x + threadIdx.x;
    const float4* p = (const float4*)g_part + (size_t)m * KC * 2;
    float s0 = 0, s1 = 0, s2 = 0, s3 = 0, s4 = 0, s5 = 0, s6 = 0, s7 = 0;
#pragma unroll
    for (int ks = 0; ks < KC; ks++) {
        float4 A = p[ks * 2];
        float4 B = p[ks * 2 + 1];
        s0 += A.x; s1 += A.y; s2 += A.z; s3 += A.w;
        s4 += B.x; s5 += B.y; s6 += B.z; s7 += B.w;
    }
    const float* c = g_corr + m * 8;
    float wd = g_wdeq;
    out[0 * M_DIM + m] = wd * (s0 + c[0]);
    out[1 * M_DIM + m] = wd * (s1 + c[1]);
    out[2 * M_DIM + m] = wd * (s2 + c[2]);
    out[3 * M_DIM + m] = wd * (s3 + c[3]);
    out[4 * M_DIM + m] = wd * (s4 + c[4]);
    out[5 * M_DIM + m] = wd * (s5 + c[5]);
    out[6 * M_DIM + m] = wd * (s6 + c[6]);
    out[7 * M_DIM + m] = wd * (s7 + c[7]);
}

// ---------------- launch (4 kernels) ----------------
extern "C" void kernel_launch(void* const* d_in, const int* in_sizes, int n_in,
                              void* d_out, int out_size) {
    const float* x = (const float*)d_in[0];    // [8, 8192]
    const float* W = (const float*)d_in[1];    // [8192, 8192]
    float* out = (float*)d_out;                // [8, 8192]

    static bool attr_done = false;
    if (!attr_done) {
        cudaFuncSetAttribute(gemv_fused_kernel, cudaFuncAttributeMaxDynamicSharedMemorySize,
                             SMEM_BYTES);
        attr_done = true;
    }

    prep_kernel<<<384, 256>>>(x, (const float4*)W);      // quant_x + sample + t-hat
    gemv_fused_kernel<<<512, 256, SMEM_BYTES>>>(W);      // ONE 256 MB pass + exact mean
    correction_kernel<<<256, 256>>>();                   // band replay
    finalize_out_kernel<<<64, 128>>>(out);               // reduce + corr + scale
}

// round 9
// speedup vs baseline: 1.1691x; 1.1691x over previous
#include <cuda_runtime.h>
#include <cstdint>

#define K_DIM 8192
#define M_DIM 8192

// gemv tiling (R3-proven, verbatim)
#define ROWTILE 64
#define KC 4
#define CHUNK (K_DIM / KC)          // 2048
#define SLICE_K 64
#define NSLICES (CHUNK / SLICE_K)   // 32
#define BUF_FLOATS 4608             // W 64*64 + X 64*8
#define NBUF 3
#define SMEM_BYTES (NBUF * BUF_FLOATS * 4)   // 55296

typedef unsigned long long ull;

// ---------------- static device scratch ----------------
__device__ float4 g_xt4[K_DIM * 2];            // x_hat transposed [K][8] (256 KB)
__device__ float g_bsum[1024];                 // exact |W| partials
__device__ float g_thresh;
__device__ float g_wdeq;
__device__ ull g_part[(size_t)M_DIM * KC * 4]; // 1 MB, f32x2-packed
__device__ unsigned g_done0 = 0;               // last-block counter (reset after use)

// ---------------- helpers ----------------
__device__ __forceinline__ void fma2(ull& acc, ull x, ull q) {
    asm("fma.rn.f32x2 %0, %1, %2, %0;" : "+l"(acc) : "l"(x), "l"(q));
}
__device__ __forceinline__ void add2(ull& acc, ull x) {
    asm("add.rn.f32x2 %0, %1, %0;" : "+l"(acc) : "l"(x));
}
__device__ __forceinline__ ull qpack(float w, float t) {
    float q = (fabsf(w) > t) ? 1.0f : 0.0f;
    q = copysignf(q, w);
    ull q2;
    asm("mov.b64 %0, {%1, %1};" : "=l"(q2) : "f"(q));
    return q2;
}
__device__ __forceinline__ void cpasync16(void* smem_dst, const void* gsrc) {
    unsigned int sa = (unsigned int)__cvta_generic_to_shared(smem_dst);
    asm volatile("cp.async.cg.shared.global [%0], [%1], 16;" :: "r"(sa), "l"(gsrc));
}
__device__ __forceinline__ void cp_commit() { asm volatile("cp.async.commit_group;"); }
__device__ __forceinline__ void cp_wait1()  { asm volatile("cp.async.wait_group 1;"); }

// ---------------- kernel 1: absmean (blocks 0-1023, BIT-EXACT R3 loop)
//                            + quant_x (blocks 1024-1151)
//                            + last-block device-side finalize_mean ----------------
__global__ void prep_kernel(const float* __restrict__ x, const float4* __restrict__ W4) {
    __shared__ float sm[8];
    __shared__ bool amLast;
    int tid = threadIdx.x;
    int lane = tid & 31, w = tid >> 5;

    if (blockIdx.x < 1024) {
        // --- exact |W| partial sums: byte-identical accumulation to R3 absmean ---
        const int stride = 1024 * 256;
        int t0 = blockIdx.x * 256 + tid;
        const float4* p = W4 + t0;
        float s = 0.f;
#pragma unroll 2
        for (int it = 0; it < 64; it += 4) {
            float4 a = __ldg(p + (size_t)(it + 0) * stride);
            float4 b = __ldg(p + (size_t)(it + 1) * stride);
            float4 c = __ldg(p + (size_t)(it + 2) * stride);
            float4 d = __ldg(p + (size_t)(it + 3) * stride);
            s += fabsf(a.x) + fabsf(a.y) + fabsf(a.z) + fabsf(a.w);
            s += fabsf(b.x) + fabsf(b.y) + fabsf(b.z) + fabsf(b.w);
            s += fabsf(c.x) + fabsf(c.y) + fabsf(c.z) + fabsf(c.w);
            s += fabsf(d.x) + fabsf(d.y) + fabsf(d.z) + fabsf(d.w);
        }
#pragma unroll
        for (int off = 16; off; off >>= 1) s += __shfl_xor_sync(0xffffffffu, s, off);
        if (lane == 0) sm[w] = s;
        __syncthreads();
        if (tid == 0) {
            float tot = 0.f;
#pragma unroll
            for (int i = 0; i < 8; i++) tot += sm[i];
            g_bsum[blockIdx.x] = tot;
        }
    } else {
        // --- activation per-group int8 quantization (unchanged math) ---
        int gid = (blockIdx.x - 1024) * 256 + tid;   // 0..32767
        int gw = gid >> 5;
        int n = gw >> 7;
        int g = gw & 127;
        int k0 = g * 64 + lane;
        float a = x[n * K_DIM + k0];
        float b = x[n * K_DIM + k0 + 32];
        float mx = fmaxf(fabsf(a), fabsf(b));
#pragma unroll
        for (int off = 16; off; off >>= 1)
            mx = fmaxf(mx, __shfl_xor_sync(0xffffffffu, mx, off));
        float sc = fmaxf(__fdiv_rn(mx, 127.0f), 1e-8f);
        float ah = rintf(__fdiv_rn(a, sc)) * sc;
        float bh = rintf(__fdiv_rn(b, sc)) * sc;
        float* xt = (float*)g_xt4;
        xt[k0 * 8 + n] = ah;
        xt[(k0 + 32) * 8 + n] = bh;
        __syncthreads();   // symmetric with other branch before counter
    }

    // --- last finished block computes the exact mean -> threshold (R3 arithmetic) ---
    if (tid == 0) {
        __threadfence();
        amLast = (atomicAdd(&g_done0, 1u) == 1151u);
    }
    __syncthreads();
    if (amLast) {
        __threadfence();
        float s = g_bsum[tid] + g_bsum[tid + 256] + g_bsum[tid + 512] + g_bsum[tid + 768];
#pragma unroll
        for (int off = 16; off; off >>= 1) s += __shfl_xor_sync(0xffffffffu, s, off);
        __syncthreads();
        if (lane == 0) sm[w] = s;
        __syncthreads();
        if (tid == 0) {
            float tot = 0.f;
#pragma unroll
            for (int i = 0; i < 8; i++) tot += sm[i];
            float mean = tot * (1.0f / 67108864.0f);
            float m = fmaxf(mean, 1e-5f);
            float s_w = __fdiv_rn(1.0f, m);
            float wdeq = __fdiv_rn(1.0f, s_w);
            g_wdeq = wdeq;
            g_thresh = 0.5f * wdeq;
            g_done0 = 0u;                       // reset for next graph replay
        }
    }
}

// ---------------- kernel 2: fused ternary GEMV (R3 verbatim — proven 47us) ----------------
__global__ void __launch_bounds__(256, 4) gemv_kernel(const float* __restrict__ W) {
    extern __shared__ float smem[];
    const float t = g_thresh;
    const int tid = threadIdx.x;
    const int lane = tid & 31, warp = tid >> 5;
    const int rt = blockIdx.x >> 2;            // 0..127 row tiles
    const int kc = blockIdx.x & 3;             // 0..3 k chunks
    const int rowbase = rt * ROWTILE;
    const int k0 = kc * CHUNK;
    const float* xt = (const float*)g_xt4;

    auto stage = [&](int s) {
        float* buf = smem + (s % NBUF) * BUF_FLOATS;
        float* bufX = buf + ROWTILE * SLICE_K;
        int base_k = k0 + s * SLICE_K;
#pragma unroll
        for (int i = 0; i < 4; i++) {
            int idx = tid + i * 256;           // 0..1023
            int r = idx >> 4, c = idx & 15;
            cpasync16(buf + r * SLICE_K + ((c ^ (r & 7)) << 2),
                      W + (size_t)(rowbase + r) * K_DIM + base_k + c * 4);
        }
        if (tid < 128) cpasync16(bufX + tid * 4, xt + (size_t)base_k * 8 + tid * 4);
    };

    ull a0 = 0, a1 = 0, a2 = 0, a3 = 0;
    ull b0 = 0, b1 = 0, b2 = 0, b3 = 0;

    stage(0); cp_commit();
    stage(1); cp_commit();

    const int sw = lane & 7;
    for (int s = 0; s < NSLICES; s++) {
        cp_wait1();
        __syncthreads();
        if (s + 2 < NSLICES) stage(s + 2);
        cp_commit();

        const float* buf = smem + (s % NBUF) * BUF_FLOATS;
        const ulonglong2* Xb = (const ulonglong2*)(buf + ROWTILE * SLICE_K);
#pragma unroll
        for (int step = 0; step < 2; step++) {
            int kk = warp * 8 + step * 4;
            int ch = kk >> 2;
            float4 wa = *(const float4*)(buf + lane * SLICE_K + ((ch ^ sw) << 2));
            float4 wb = *(const float4*)(buf + (lane + 32) * SLICE_K + ((ch ^ sw) << 2));
            float wae[4] = {wa.x, wa.y, wa.z, wa.w};
            float wbe[4] = {wb.x, wb.y, wb.z, wb.w};
#pragma unroll
            for (int e = 0; e < 4; e++) {
                ulonglong2 x0 = Xb[(kk + e) * 2];
                ulonglong2 x1 = Xb[(kk + e) * 2 + 1];
                ull qa = qpack(wae[e], t);
                ull qb = qpack(wbe[e], t);
                fma2(a0, x0.x, qa); fma2(a1, x0.y, qa);
                fma2(a2, x1.x, qa); fma2(a3, x1.y, qa);
                fma2(b0, x0.x, qb); fma2(b1, x0.y, qb);
                fma2(b2, x1.x, qb); fma2(b3, x1.y, qb);
            }
        }
    }

    // ---- in-block cross-warp reduction: 8 partials/row -> 1 ----
    __syncthreads();
    ulonglong2* s2 = (ulonglong2*)smem;
    s2[(warp * 64 + lane) * 2]          = make_ulonglong2(a0, a1);
    s2[(warp * 64 + lane) * 2 + 1]      = make_ulonglong2(a2, a3);
    s2[(warp * 64 + lane + 32) * 2]     = make_ulonglong2(b0, b1);
    s2[(warp * 64 + lane + 32) * 2 + 1] = make_ulonglong2(b2, b3);
    __syncthreads();
    if (tid < 64) {
        ull r0 = 0, r1 = 0, r2 = 0, r3 = 0;
#pragma unroll
        for (int w = 0; w < 8; w++) {
            ulonglong2 u0 = s2[(w * 64 + tid) * 2];
            ulonglong2 u1 = s2[(w * 64 + tid) * 2 + 1];
            add2(r0, u0.x); add2(r1, u0.y);
            add2(r2, u1.x); add2(r3, u1.y);
        }
        ulonglong2* P = (ulonglong2*)g_part;
        size_t p = ((size_t)(rowbase + tid) * KC + kc) * 2;
        P[p]     = make_ulonglong2(r0, r1);
        P[p + 1] = make_ulonglong2(r2, r3);
    }
}

// ---------------- kernel 3: reduce KC partials, apply w_deq (16384 threads, MLP 4) ----------------
__global__ void finalize_out_kernel(float* __restrict__ out) {
    int gid = blockIdx.x * blockDim.x + threadIdx.x;   // 0..16383
    int m = gid >> 1;                                  // 0..8191
    int h = gid & 1;                                   // n-half: 0 -> n0..3, 1 -> n4..7
    const float4* F = (const float4*)g_part;
    size_t base = (size_t)m * KC * 2 + h;
    float4 A = F[base + 0 * 2];
    float4 B = F[base + 1 * 2];
    float4 C = F[base + 2 * 2];
    float4 D = F[base + 3 * 2];
    float s0 = A.x + B.x + C.x + D.x;
    float s1 = A.y + B.y + C.y + D.y;
    float s2 = A.z + B.z + C.z + D.z;
    float s3 = A.w + B.w + C.w + D.w;
    float wd = g_wdeq;
    int n0 = h * 4;
    out[(n0 + 0) * M_DIM + m] = wd * s0;
    out[(n0 + 1) * M_DIM + m] = wd * s1;
    out[(n0 + 2) * M_DIM + m] = wd * s2;
    out[(n0 + 3) * M_DIM + m] = wd * s3;
}

// ---------------- launch (3 kernels) ----------------
extern "C" void kernel_launch(void* const* d_in, const int* in_sizes, int n_in,
                              void* d_out, int out_size) {
    const float* x = (const float*)d_in[0];    // [8, 8192]
    const float* W = (const float*)d_in[1];    // [8192, 8192]
    float* out = (float*)d_out;                // [8, 8192]

    static bool attr_done = false;
    if (!attr_done) {
        cudaFuncSetAttribute(gemv_kernel, cudaFuncAttributeMaxDynamicSharedMemorySize,
                             SMEM_BYTES);
        attr_done = true;
    }

    prep_kernel<<<1152, 256>>>(x, (const float4*)W);   // absmean + quant_x + mean finalize
    gemv_kernel<<<512, 256, SMEM_BYTES>>>(W);          // pass 2: fused quant + GEMV
    finalize_out_kernel<<<64, 256>>>(out);             // reduce + scale
}

// round 10
// speedup vs baseline: 1.2183x; 1.0421x over previous
#include <cuda_runtime.h>
#include <cstdint>

#define K_DIM 8192
#define M_DIM 8192

// gemv tiling (R3-proven, verbatim)
#define ROWTILE 64
#define KC 4
#define CHUNK (K_DIM / KC)          // 2048
#define SLICE_K 64
#define NSLICES (CHUNK / SLICE_K)   // 32
#define BUF_FLOATS 4608             // W 64*64 + X 64*8
#define NBUF 3
#define SMEM_BYTES (NBUF * BUF_FLOATS * 4)   // 55296

typedef unsigned long long ull;

// ---------------- static device scratch ----------------
__device__ float4 g_xt4[K_DIM * 2];            // x_hat transposed [K][8] (256 KB)
__device__ float g_bsum[1024];                 // exact |W| partials
__device__ float g_thresh;
__device__ float g_wdeq;
__device__ ull g_part[(size_t)M_DIM * KC * 4]; // 1 MB, f32x2-packed
__device__ unsigned g_done0 = 0;               // last-block counter (reset after use)

// ---------------- helpers ----------------
__device__ __forceinline__ void fma2(ull& acc, ull x, ull q) {
    asm("fma.rn.f32x2 %0, %1, %2, %0;" : "+l"(acc) : "l"(x), "l"(q));
}
__device__ __forceinline__ void add2(ull& acc, ull x) {
    asm("add.rn.f32x2 %0, %1, %0;" : "+l"(acc) : "l"(x));
}
__device__ __forceinline__ ull qpack(float w, float t) {
    float q = (fabsf(w) > t) ? 1.0f : 0.0f;
    q = copysignf(q, w);
    ull q2;
    asm("mov.b64 %0, {%1, %1};" : "=l"(q2) : "f"(q));
    return q2;
}
__device__ __forceinline__ void cpasync16(void* smem_dst, const void* gsrc) {
    unsigned int sa = (unsigned int)__cvta_generic_to_shared(smem_dst);
    asm volatile("cp.async.cg.shared.global [%0], [%1], 16;" :: "r"(sa), "l"(gsrc));
}
__device__ __forceinline__ void cp_commit() { asm volatile("cp.async.commit_group;"); }
__device__ __forceinline__ void cp_wait1()  { asm volatile("cp.async.wait_group 1;"); }

// ---------------- kernel 1: absmean (blocks 0-1023, BIT-EXACT R3 loop)
//                            + quant_x (blocks 1024-1151)
//                            + last-block device-side finalize_mean ----------------
// NOTE: the absmean `it` loop sweeps W in ascending 4 MB slabs; with ~all blocks
// resident the grid walks W front-to-back, leaving the LAST ~126 MB of W hot in L2.
__global__ void prep_kernel(const float* __restrict__ x, const float4* __restrict__ W4) {
    __shared__ float sm[8];
    __shared__ bool amLast;
    int tid = threadIdx.x;
    int lane = tid & 31, w = tid >> 5;

    if (blockIdx.x < 1024) {
        // --- exact |W| partial sums: byte-identical accumulation to R3 absmean ---
        const int stride = 1024 * 256;
        int t0 = blockIdx.x * 256 + tid;
        const float4* p = W4 + t0;
        float s = 0.f;
#pragma unroll 2
        for (int it = 0; it < 64; it += 4) {
            float4 a = __ldg(p + (size_t)(it + 0) * stride);
            float4 b = __ldg(p + (size_t)(it + 1) * stride);
            float4 c = __ldg(p + (size_t)(it + 2) * stride);
            float4 d = __ldg(p + (size_t)(it + 3) * stride);
            s += fabsf(a.x) + fabsf(a.y) + fabsf(a.z) + fabsf(a.w);
            s += fabsf(b.x) + fabsf(b.y) + fabsf(b.z) + fabsf(b.w);
            s += fabsf(c.x) + fabsf(c.y) + fabsf(c.z) + fabsf(c.w);
            s += fabsf(d.x) + fabsf(d.y) + fabsf(d.z) + fabsf(d.w);
        }
#pragma unroll
        for (int off = 16; off; off >>= 1) s += __shfl_xor_sync(0xffffffffu, s, off);
        if (lane == 0) sm[w] = s;
        __syncthreads();
        if (tid == 0) {
            float tot = 0.f;
#pragma unroll
            for (int i = 0; i < 8; i++) tot += sm[i];
            g_bsum[blockIdx.x] = tot;
        }
    } else {
        // --- activation per-group int8 quantization (unchanged math) ---
        int gid = (blockIdx.x - 1024) * 256 + tid;   // 0..32767
        int gw = gid >> 5;
        int n = gw >> 7;
        int g = gw & 127;
        int k0 = g * 64 + lane;
        float a = x[n * K_DIM + k0];
        float b = x[n * K_DIM + k0 + 32];
        float mx = fmaxf(fabsf(a), fabsf(b));
#pragma unroll
        for (int off = 16; off; off >>= 1)
            mx = fmaxf(mx, __shfl_xor_sync(0xffffffffu, mx, off));
        float sc = fmaxf(__fdiv_rn(mx, 127.0f), 1e-8f);
        float ah = rintf(__fdiv_rn(a, sc)) * sc;
        float bh = rintf(__fdiv_rn(b, sc)) * sc;
        float* xt = (float*)g_xt4;
        xt[k0 * 8 + n] = ah;
        xt[(k0 + 32) * 8 + n] = bh;
        __syncthreads();   // symmetric with other branch before counter
    }

    // --- last finished block computes the exact mean -> threshold (R3 arithmetic) ---
    if (tid == 0) {
        __threadfence();
        amLast = (atomicAdd(&g_done0, 1u) == 1151u);
    }
    __syncthreads();
    if (amLast) {
        __threadfence();
        float s = g_bsum[tid] + g_bsum[tid + 256] + g_bsum[tid + 512] + g_bsum[tid + 768];
#pragma unroll
        for (int off = 16; off; off >>= 1) s += __shfl_xor_sync(0xffffffffu, s, off);
        __syncthreads();
        if (lane == 0) sm[w] = s;
        __syncthreads();
        if (tid == 0) {
            float tot = 0.f;
#pragma unroll
            for (int i = 0; i < 8; i++) tot += sm[i];
            float mean = tot * (1.0f / 67108864.0f);
            float m = fmaxf(mean, 1e-5f);
            float s_w = __fdiv_rn(1.0f, m);
            float wdeq = __fdiv_rn(1.0f, s_w);
            g_wdeq = wdeq;
            g_thresh = 0.5f * wdeq;
            g_done0 = 0u;                       // reset for next graph replay
        }
    }
}

// ---------------- kernel 2: fused ternary GEMV (R3 loop; REVERSED row-tile order) ----------------
// Row tiles are visited high-to-low so the tail of W (still L2-resident from
// prep's ascending sweep) is read via L2 instead of DRAM.
__global__ void __launch_bounds__(256, 4) gemv_kernel(const float* __restrict__ W) {
    extern __shared__ float smem[];
    const float t = g_thresh;
    const int tid = threadIdx.x;
    const int lane = tid & 31, warp = tid >> 5;
    const int rt = 127 - (blockIdx.x >> 2);    // REVERSED: high rows first (L2-hot)
    const int kc = blockIdx.x & 3;             // 0..3 k chunks
    const int rowbase = rt * ROWTILE;
    const int k0 = kc * CHUNK;
    const float* xt = (const float*)g_xt4;

    auto stage = [&](int s) {
        float* buf = smem + (s % NBUF) * BUF_FLOATS;
        float* bufX = buf + ROWTILE * SLICE_K;
        int base_k = k0 + s * SLICE_K;
#pragma unroll
        for (int i = 0; i < 4; i++) {
            int idx = tid + i * 256;           // 0..1023
            int r = idx >> 4, c = idx & 15;
            cpasync16(buf + r * SLICE_K + ((c ^ (r & 7)) << 2),
                      W + (size_t)(rowbase + r) * K_DIM + base_k + c * 4);
        }
        if (tid < 128) cpasync16(bufX + tid * 4, xt + (size_t)base_k * 8 + tid * 4);
    };

    ull a0 = 0, a1 = 0, a2 = 0, a3 = 0;
    ull b0 = 0, b1 = 0, b2 = 0, b3 = 0;

    stage(0); cp_commit();
    stage(1); cp_commit();

    const int sw = lane & 7;
    for (int s = 0; s < NSLICES; s++) {
        cp_wait1();
        __syncthreads();
        if (s + 2 < NSLICES) stage(s + 2);
        cp_commit();

        const float* buf = smem + (s % NBUF) * BUF_FLOATS;
        const ulonglong2* Xb = (const ulonglong2*)(buf + ROWTILE * SLICE_K);
#pragma unroll
        for (int step = 0; step < 2; step++) {
            int kk = warp * 8 + step * 4;
            int ch = kk >> 2;
            float4 wa = *(const float4*)(buf + lane * SLICE_K + ((ch ^ sw) << 2));
            float4 wb = *(const float4*)(buf + (lane + 32) * SLICE_K + ((ch ^ sw) << 2));
            float wae[4] = {wa.x, wa.y, wa.z, wa.w};
            float wbe[4] = {wb.x, wb.y, wb.z, wb.w};
#pragma unroll
            for (int e = 0; e < 4; e++) {
                ulonglong2 x0 = Xb[(kk + e) * 2];
                ulonglong2 x1 = Xb[(kk + e) * 2 + 1];
                ull qa = qpack(wae[e], t);
                ull qb = qpack(wbe[e], t);
                fma2(a0, x0.x, qa); fma2(a1, x0.y, qa);
                fma2(a2, x1.x, qa); fma2(a3, x1.y, qa);
                fma2(b0, x0.x, qb); fma2(b1, x0.y, qb);
                fma2(b2, x1.x, qb); fma2(b3, x1.y, qb);
            }
        }
    }

    // ---- in-block cross-warp reduction: 8 partials/row -> 1 ----
    __syncthreads();
    ulonglong2* s2 = (ulonglong2*)smem;
    s2[(warp * 64 + lane) * 2]          = make_ulonglong2(a0, a1);
    s2[(warp * 64 + lane) * 2 + 1]      = make_ulonglong2(a2, a3);
    s2[(warp * 64 + lane + 32) * 2]     = make_ulonglong2(b0, b1);
    s2[(warp * 64 + lane + 32) * 2 + 1] = make_ulonglong2(b2, b3);
    __syncthreads();
    if (tid < 64) {
        ull r0 = 0, r1 = 0, r2 = 0, r3 = 0;
#pragma unroll
        for (int w = 0; w < 8; w++) {
            ulonglong2 u0 = s2[(w * 64 + tid) * 2];
            ulonglong2 u1 = s2[(w * 64 + tid) * 2 + 1];
            add2(r0, u0.x); add2(r1, u0.y);
            add2(r2, u1.x); add2(r3, u1.y);
        }
        ulonglong2* P = (ulonglong2*)g_part;
        size_t p = ((size_t)(rowbase + tid) * KC + kc) * 2;
        P[p]     = make_ulonglong2(r0, r1);
        P[p + 1] = make_ulonglong2(r2, r3);
    }
}

// ---------------- kernel 3: reduce KC partials, apply w_deq (16384 threads) ----------------
__global__ void finalize_out_kernel(float* __restrict__ out) {
    int gid = blockIdx.x * blockDim.x + threadIdx.x;   // 0..16383
    int m = gid >> 1;                                  // 0..8191
    int h = gid & 1;                                   // n-half: 0 -> n0..3, 1 -> n4..7
    const float4* F = (const float4*)g_part;
    size_t base = (size_t)m * KC * 2 + h;
    float4 A = F[base + 0 * 2];
    float4 B = F[base + 1 * 2];
    float4 C = F[base + 2 * 2];
    float4 D = F[base + 3 * 2];
    float s0 = A.x + B.x + C.x + D.x;
    float s1 = A.y + B.y + C.y + D.y;
    float s2 = A.z + B.z + C.z + D.z;
    float s3 = A.w + B.w + C.w + D.w;
    float wd = g_wdeq;
    int n0 = h * 4;
    out[(n0 + 0) * M_DIM + m] = wd * s0;
    out[(n0 + 1) * M_DIM + m] = wd * s1;
    out[(n0 + 2) * M_DIM + m] = wd * s2;
    out[(n0 + 3) * M_DIM + m] = wd * s3;
}

// ---------------- launch (3 kernels) ----------------
extern "C" void kernel_launch(void* const* d_in, const int* in_sizes, int n_in,
                              void* d_out, int out_size) {
    const float* x = (const float*)d_in[0];    // [8, 8192]
    const float* W = (const float*)d_in[1];    // [8192, 8192]
    float* out = (float*)d_out;                // [8, 8192]

    static bool attr_done = false;
    if (!attr_done) {
        cudaFuncSetAttribute(gemv_kernel, cudaFuncAttributeMaxDynamicSharedMemorySize,
                             SMEM_BYTES);
        attr_done = true;
    }

    prep_kernel<<<1152, 256>>>(x, (const float4*)W);   // absmean + quant_x + mean finalize
    gemv_kernel<<<512, 256, SMEM_BYTES>>>(W);          // pass 2, tail-first for L2 reuse
    finalize_out_kernel<<<64, 256>>>(out);             // reduce + scale
}